// round 2
// baseline (speedup 1.0000x reference)
#include <cuda_runtime.h>
#include <math.h>

#define Tt 128
#define Bb 32
#define Ii 256
#define Hh 1024
#define Oo 128
#define TBm (Tt*Bb)      /* 4096 */
#define BHm (Bb*Hh)      /* 32768 */

// ---------------- scratch (device globals; no allocations allowed) ----------------
static __device__ float g_Hstate[(Tt+1)*BHm];      // [t][b][h], t=0..T
static __device__ float g_hT[2*Hh*Bb];             // ping-pong transposed state [h][b]
static __device__ float g_Xin[(size_t)TBm*Hh];     // x @ W_in^T, [t*B+b][h]
static __device__ float g_Zl[(size_t)TBm*Hh];      // target @ W_out
static __device__ float g_Cb[(size_t)TBm*Hh];      // c then A (in-place)
static __device__ float g_Mm[(size_t)Hh*Hh];       // W_out^T W_out
static __device__ float g_Err[TBm*Oo];
static __device__ float g_Part[4*(size_t)Hh*Hh];   // split-K partials

// ---------------- generic fp32 tiled GEMM ----------------
// MODE 0 = NN: C[m,n] = sum_k A[m,k]*B[k,n]   (A stride Kd, B stride Nd)
// MODE 1 = NT: C[m,n] = sum_k A[m,k]*B[n,k]   (A stride Kd, B stride Kd)
// MODE 2 = TN: C[m,n] = sum_k A[k,m]*B[k,n]   (A stride Md, B stride Nd)
// If gridDim.z > 1: writes raw partials to Cpart[z][M*N], alpha applied in reduce.
template<int MODE, int BM, int BN, int BK, int TMv, int TNv>
__global__ __launch_bounds__(256) void gemm_k(
    const float* __restrict__ A, const float* __restrict__ B,
    float* __restrict__ C, float* __restrict__ Cpart,
    int Md, int Nd, int Kd, float alpha, int kslice)
{
    __shared__ float As[BK][BM];
    __shared__ float Bs[BK][BN];
    const int t  = threadIdx.x;
    const int tx = t & 15, ty = t >> 4;
    const int m0 = blockIdx.y * BM, n0 = blockIdx.x * BN;
    const int kbeg = blockIdx.z * kslice;
    const int kend = kbeg + kslice;

    float acc[TMv][TNv];
    #pragma unroll
    for (int i = 0; i < TMv; i++)
        #pragma unroll
        for (int j = 0; j < TNv; j++) acc[i][j] = 0.f;

    for (int kk = kbeg; kk < kend; kk += BK) {
        // ---- load A tile ----
        if (MODE == 0 || MODE == 1) {               // A[m,k], row stride Kd
            const int kv = BK / 4;
            int m = t / kv, kq = (t % kv) * 4;
            float4 v = *(const float4*)&A[(size_t)(m0 + m) * Kd + kk + kq];
            As[kq + 0][m] = v.x; As[kq + 1][m] = v.y;
            As[kq + 2][m] = v.z; As[kq + 3][m] = v.w;
        } else {                                    // A[k,m], row stride Md
            const int mv = BM / 4;
            int k = t / mv, mq = (t % mv) * 4;
            *(float4*)&As[k][mq] = *(const float4*)&A[(size_t)(kk + k) * Md + m0 + mq];
        }
        // ---- load B tile ----
        if (MODE == 0 || MODE == 2) {               // B[k,n], row stride Nd
            const int nv = BN / 4;
            int k = t / nv, nq = (t % nv) * 4;
            *(float4*)&Bs[k][nq] = *(const float4*)&B[(size_t)(kk + k) * Nd + n0 + nq];
        } else {                                    // B[n,k], row stride Kd
            const int kv = BK / 4;
            int n = t / kv, kq = (t % kv) * 4;
            float4 v = *(const float4*)&B[(size_t)(n0 + n) * Kd + kk + kq];
            Bs[kq + 0][n] = v.x; Bs[kq + 1][n] = v.y;
            Bs[kq + 2][n] = v.z; Bs[kq + 3][n] = v.w;
        }
        __syncthreads();

        #pragma unroll
        for (int k = 0; k < BK; k++) {
            float a[TMv], bb[TNv];
            #pragma unroll
            for (int i = 0; i < TMv; i += 4) {
                float4 v = *(const float4*)&As[k][ty * TMv + i];
                a[i] = v.x; a[i + 1] = v.y; a[i + 2] = v.z; a[i + 3] = v.w;
            }
            #pragma unroll
            for (int j = 0; j < TNv; j += 4) {
                float4 v = *(const float4*)&Bs[k][tx * TNv + j];
                bb[j] = v.x; bb[j + 1] = v.y; bb[j + 2] = v.z; bb[j + 3] = v.w;
            }
            #pragma unroll
            for (int i = 0; i < TMv; i++)
                #pragma unroll
                for (int j = 0; j < TNv; j++)
                    acc[i][j] = fmaf(a[i], bb[j], acc[i][j]);
        }
        __syncthreads();
    }

    float scale = alpha;
    float* dst = C;
    if (gridDim.z > 1) { dst = Cpart + (size_t)blockIdx.z * Md * Nd; scale = 1.f; }
    #pragma unroll
    for (int i = 0; i < TMv; i++) {
        size_t row = (size_t)(m0 + ty * TMv + i) * Nd + n0 + tx * TNv;
        #pragma unroll
        for (int j = 0; j < TNv; j += 4) {
            float4 v;
            v.x = scale * acc[i][j];     v.y = scale * acc[i][j + 1];
            v.z = scale * acc[i][j + 2]; v.w = scale * acc[i][j + 3];
            *(float4*)&dst[row + j] = v;
        }
    }
}

// ---------------- recurrent step: h_new = tanh(Xin_t + h @ W_hh^T) ----------------
// grid 128 blocks x 128 threads. Block covers 8 h (4 warps x 2 h), warp = 32 b lanes.
// h state kept transposed [H][B] for coalesced loads; staged into smem as [b][k]
// with row stride 260 (16B-aligned, stride mod 32 == 4 -> conflict-free float4 LDS).
__global__ __launch_bounds__(128) void rnn_step_k(
    const float* __restrict__ hT_in, const float* __restrict__ W_hh,
    const float* __restrict__ Xin_t, float* __restrict__ hT_out,
    float* __restrict__ Hout)
{
    __shared__ float hS[32][260];
    const int t = threadIdx.x;
    const int lane = t & 31, w = t >> 5;
    const int h0 = blockIdx.x * 8 + w * 2;

    float acc0 = 0.f, acc1 = 0.f;
    for (int k0 = 0; k0 < Hh; k0 += 256) {
        // stage hT chunk [256 k][32 b] -> hS[b][k]
        #pragma unroll
        for (int r = 0; r < 256; r += 16) {
            int kk = r + (t >> 3);
            int bq = (t & 7) * 4;
            float4 v = *(const float4*)&hT_in[(k0 + kk) * Bb + bq];
            hS[bq + 0][kk] = v.x; hS[bq + 1][kk] = v.y;
            hS[bq + 2][kk] = v.z; hS[bq + 3][kk] = v.w;
        }
        __syncthreads();
        const float4* w0p = (const float4*)&W_hh[(size_t)h0 * Hh + k0];
        const float4* w1p = (const float4*)&W_hh[(size_t)(h0 + 1) * Hh + k0];
        #pragma unroll 8
        for (int k = 0; k < 256; k += 4) {
            float4 hv = *(const float4*)&hS[lane][k];
            float4 wa = __ldg(&w0p[k >> 2]);
            float4 wb = __ldg(&w1p[k >> 2]);
            acc0 = fmaf(hv.x, wa.x, acc0); acc0 = fmaf(hv.y, wa.y, acc0);
            acc0 = fmaf(hv.z, wa.z, acc0); acc0 = fmaf(hv.w, wa.w, acc0);
            acc1 = fmaf(hv.x, wb.x, acc1); acc1 = fmaf(hv.y, wb.y, acc1);
            acc1 = fmaf(hv.z, wb.z, acc1); acc1 = fmaf(hv.w, wb.w, acc1);
        }
        __syncthreads();
    }
    const int b = lane;
    float v0 = tanhf(acc0 + Xin_t[b * Hh + h0]);
    float v1 = tanhf(acc1 + Xin_t[b * Hh + h0 + 1]);
    hT_out[(h0) * Bb + b] = v0;
    hT_out[(h0 + 1) * Bb + b] = v1;
    Hout[b * Hh + h0] = v0;
    Hout[b * Hh + h0 + 1] = v1;
}

// ---------------- small elementwise kernels ----------------
__global__ void transpose_h0_k(const float* __restrict__ h0,
                               float* __restrict__ hT, float* __restrict__ Hst)
{
    int idx = blockIdx.x * blockDim.x + threadIdx.x;   // b*H + h
    int b = idx >> 10, h = idx & 1023;
    float v = h0[idx];
    Hst[idx] = v;
    hT[h * Bb + b] = v;
}

// c = (Hnew@M - Zl) * (1 - Hnew^2)
__global__ void c_post_k(float* __restrict__ Cb, const float* __restrict__ Zl,
                         const float* __restrict__ Hst)
{
    size_t idx = (size_t)blockIdx.x * blockDim.x + threadIdx.x;
    float hn = Hst[BHm + idx];
    Cb[idx] = (Cb[idx] - Zl[idx]) * (1.f - hn * hn);
}

__global__ void err_k(const float* __restrict__ ys, const float* __restrict__ tgt,
                      float* __restrict__ e)
{
    int idx = blockIdx.x * blockDim.x + threadIdx.x;
    e[idx] = ys[idx] - tgt[idx];
}

// A[s] = c[s] + D[s+1]*A[s+1],  D[s+1] = diag(W_hh) * (1 - Hstate[s+1]^2)
__global__ void back_scan_k(float* __restrict__ Cb, const float* __restrict__ Hst,
                            const float* __restrict__ Whh)
{
    int idx = blockIdx.x * blockDim.x + threadIdx.x;   // b*H + h
    int h = idx & 1023;
    float dw = Whh[(size_t)h * Hh + h];
    float a = Cb[(size_t)(Tt - 1) * BHm + idx];
    for (int s = Tt - 2; s >= 0; s--) {
        float hn = Hst[(size_t)(s + 1) * BHm + idx];
        float d = dw * (1.f - hn * hn);
        a = Cb[(size_t)s * BHm + idx] + d * a;
        Cb[(size_t)s * BHm + idx] = a;
    }
}

__global__ void reduce_k(const float* __restrict__ part, float* __restrict__ out,
                         int MN, int S, float alpha)
{
    int i = blockIdx.x * blockDim.x + threadIdx.x;
    if (i < MN) {
        float s = 0.f;
        for (int z = 0; z < S; z++) s += part[(size_t)z * MN + i];
        out[i] = alpha * s;
    }
}

__global__ void copy_k(const float* __restrict__ src, float* __restrict__ dst)
{
    int i = blockIdx.x * blockDim.x + threadIdx.x;
    dst[i] = src[i];
}

// ---------------- orchestration ----------------
extern "C" void kernel_launch(void* const* d_in, const int* in_sizes, int n_in,
                              void* d_out, int out_size)
{
    const float* x    = (const float*)d_in[0];   // [T,B,I]
    const float* tgt  = (const float*)d_in[1];   // [T,B,O]
    const float* h0   = (const float*)d_in[2];   // [B,H]
    const float* Win  = (const float*)d_in[3];   // [H,I]
    const float* Whh  = (const float*)d_in[4];   // [H,H]
    const float* Wout = (const float*)d_in[5];   // [O,H]

    float* out   = (float*)d_out;
    float* ys    = out;                      // [T*B, O]
    float* hf    = ys + (size_t)TBm * Oo;    // [B, H]
    float* gwout = hf + BHm;                 // [O, H]
    float* gwih  = gwout + (size_t)Oo * Hh;  // [H, I]
    float* gwhh  = gwih + (size_t)Hh * Ii;   // [H, H]

    float *Hst, *hT, *Xin, *Zl, *Cb, *Mm, *Err, *Part;
    cudaGetSymbolAddress((void**)&Hst,  g_Hstate);
    cudaGetSymbolAddress((void**)&hT,   g_hT);
    cudaGetSymbolAddress((void**)&Xin,  g_Xin);
    cudaGetSymbolAddress((void**)&Zl,   g_Zl);
    cudaGetSymbolAddress((void**)&Cb,   g_Cb);
    cudaGetSymbolAddress((void**)&Mm,   g_Mm);
    cudaGetSymbolAddress((void**)&Err,  g_Err);
    cudaGetSymbolAddress((void**)&Part, g_Part);

    // Xin = x @ Win^T   (NT: M=4096, N=1024, K=256)
    gemm_k<1,128,128,8,8,8><<<dim3(Hh/128, TBm/128, 1), 256>>>(
        x, Win, Xin, nullptr, TBm, Hh, Ii, 1.f, Ii);
    // Zl = target @ Wout  (NN: M=4096, N=1024, K=128)
    gemm_k<0,128,128,8,8,8><<<dim3(Hh/128, TBm/128, 1), 256>>>(
        tgt, Wout, Zl, nullptr, TBm, Hh, Oo, 1.f, Oo);
    // M = Wout^T @ Wout  (TN: M=N=1024, K=128)
    gemm_k<2,64,64,16,4,4><<<dim3(Hh/64, Hh/64, 1), 256>>>(
        Wout, Wout, Mm, nullptr, Hh, Hh, Oo, 1.f, Oo);
    // seed state
    transpose_h0_k<<<BHm/256, 256>>>(h0, hT, Hst);

    // sequential forward: h_{t+1} = tanh(Xin[t] + h_t @ Whh^T)
    for (int t = 0; t < Tt; t++) {
        rnn_step_k<<<128, 128>>>(
            hT + (size_t)(t & 1) * Hh * Bb, Whh, Xin + (size_t)t * BHm,
            hT + (size_t)((t + 1) & 1) * Hh * Bb, Hst + (size_t)(t + 1) * BHm);
    }

    // c = (Hnew @ M - Zl) * (1 - Hnew^2)
    gemm_k<0,128,128,8,8,8><<<dim3(Hh/128, TBm/128, 1), 256>>>(
        Hst + BHm, Mm, Cb, nullptr, TBm, Hh, Hh, 1.f, Hh);
    c_post_k<<<((size_t)TBm*Hh)/256, 256>>>(Cb, Zl, Hst);

    // ys = Hnew @ Wout^T  (NT: M=4096, N=128, K=1024)
    gemm_k<1,64,64,16,4,4><<<dim3(Oo/64, TBm/64, 1), 256>>>(
        Hst + BHm, Wout, ys, nullptr, TBm, Oo, Hh, 1.f, Hh);
    err_k<<<(TBm*Oo)/256, 256>>>(ys, tgt, Err);

    // backward scan: A[s] = c[s] + D[s+1]*A[s+1] (in-place in Cb)
    back_scan_k<<<BHm/256, 256>>>(Cb, Hst, Whh);

    // g_wih = (1e-3/B) * A^T @ x   (TN: M=1024, N=256, K=4096, split 4)
    gemm_k<2,64,64,16,4,4><<<dim3(Ii/64, Hh/64, 4), 256>>>(
        Cb, x, nullptr, Part, Hh, Ii, TBm, 0.f, TBm/4);
    reduce_k<<<(Hh*Ii + 255)/256, 256>>>(Part, gwih, Hh*Ii, 4, 1e-3f/Bb);

    // g_whh = (1e-5/B) * A^T @ Hprev  (TN: M=N=1024, K=4096, split 4)
    gemm_k<2,128,128,8,8,8><<<dim3(Hh/128, Hh/128, 4), 256>>>(
        Cb, Hst, nullptr, Part, Hh, Hh, TBm, 0.f, TBm/4);
    reduce_k<<<(Hh*Hh + 255)/256, 256>>>(Part, gwhh, Hh*Hh, 4, 1e-5f/Bb);

    // g_wout = (1/B) * Err^T @ Hnew  (TN: M=128, N=1024, K=4096, split 8)
    gemm_k<2,64,64,16,4,4><<<dim3(Hh/64, Oo/64, 8), 256>>>(
        Err, Hst + BHm, nullptr, Part, Oo, Hh, TBm, 0.f, TBm/8);
    reduce_k<<<(Oo*Hh + 255)/256, 256>>>(Part, gwout, Oo*Hh, 8, 1.f/Bb);

    // h_f
    copy_k<<<BHm/256, 256>>>(Hst + (size_t)Tt * BHm, hf);
}

// round 4
// speedup vs baseline: 1.3865x; 1.3865x over previous
#include <cuda_runtime.h>
#include <math.h>

#define Tt 128
#define Bb 32
#define Ii 256
#define Hh 1024
#define Oo 128
#define TBm (Tt*Bb)      /* 4096 */
#define BHm (Bb*Hh)      /* 32768 */
#define NBLK 128
#define HSTR 36          /* hS row stride: multiple of 4 -> float4-aligned */

// ---------------- scratch (device globals; no allocations allowed) ----------------
static __device__ float g_Hstate[(Tt+1)*BHm];      // [t][b][h], t=0..T
static __device__ float g_hT[2*Hh*Bb];             // ping-pong transposed state [h][b]
static __device__ float g_Xin[(size_t)TBm*Hh];     // x @ W_in^T, [t*B+b][h]
static __device__ float g_Cb[(size_t)TBm*Hh];      // c then A (in-place)
static __device__ float g_Err[TBm*Oo];
static __device__ float g_Part[4*(size_t)Hh*Hh];   // split-K partials
static __device__ unsigned g_barc = 0;
static __device__ unsigned g_barg = 0;

// ---------------- generic fp32 tiled GEMM ----------------
// MODE 0 = NN: C[m,n] = sum_k A[m,k]*B[k,n]   (A stride Kd, B stride Nd)
// MODE 1 = NT: C[m,n] = sum_k A[m,k]*B[n,k]   (A stride Kd, B stride Kd)
// MODE 2 = TN: C[m,n] = sum_k A[k,m]*B[k,n]   (A stride Md, B stride Nd)
// If gridDim.z > 1: writes raw partials to Cpart[z][M*N], alpha applied in reduce.
template<int MODE, int BM, int BN, int BK, int TMv, int TNv>
__global__ __launch_bounds__(256) void gemm_k(
    const float* __restrict__ A, const float* __restrict__ B,
    float* __restrict__ C, float* __restrict__ Cpart,
    int Md, int Nd, int Kd, float alpha, int kslice)
{
    __shared__ float As[BK][BM];
    __shared__ float Bs[BK][BN];
    const int t  = threadIdx.x;
    const int tx = t & 15, ty = t >> 4;
    const int m0 = blockIdx.y * BM, n0 = blockIdx.x * BN;
    const int kbeg = blockIdx.z * kslice;
    const int kend = kbeg + kslice;

    float acc[TMv][TNv];
    #pragma unroll
    for (int i = 0; i < TMv; i++)
        #pragma unroll
        for (int j = 0; j < TNv; j++) acc[i][j] = 0.f;

    for (int kk = kbeg; kk < kend; kk += BK) {
        // ---- load A tile ----
        if (MODE == 0 || MODE == 1) {               // A[m,k], row stride Kd
            const int kv = BK / 4;
            int m = t / kv, kq = (t % kv) * 4;
            float4 v = *(const float4*)&A[(size_t)(m0 + m) * Kd + kk + kq];
            As[kq + 0][m] = v.x; As[kq + 1][m] = v.y;
            As[kq + 2][m] = v.z; As[kq + 3][m] = v.w;
        } else {                                    // A[k,m], row stride Md
            const int mv = BM / 4;
            int k = t / mv, mq = (t % mv) * 4;
            *(float4*)&As[k][mq] = *(const float4*)&A[(size_t)(kk + k) * Md + m0 + mq];
        }
        // ---- load B tile ----
        if (MODE == 0 || MODE == 2) {               // B[k,n], row stride Nd
            const int nv = BN / 4;
            int k = t / nv, nq = (t % nv) * 4;
            *(float4*)&Bs[k][nq] = *(const float4*)&B[(size_t)(kk + k) * Nd + n0 + nq];
        } else {                                    // B[n,k], row stride Kd
            const int kv = BK / 4;
            int n = t / kv, kq = (t % kv) * 4;
            float4 v = *(const float4*)&B[(size_t)(n0 + n) * Kd + kk + kq];
            Bs[kq + 0][n] = v.x; Bs[kq + 1][n] = v.y;
            Bs[kq + 2][n] = v.z; Bs[kq + 3][n] = v.w;
        }
        __syncthreads();

        #pragma unroll
        for (int k = 0; k < BK; k++) {
            float a[TMv], bb[TNv];
            #pragma unroll
            for (int i = 0; i < TMv; i += 4) {
                float4 v = *(const float4*)&As[k][ty * TMv + i];
                a[i] = v.x; a[i + 1] = v.y; a[i + 2] = v.z; a[i + 3] = v.w;
            }
            #pragma unroll
            for (int j = 0; j < TNv; j += 4) {
                float4 v = *(const float4*)&Bs[k][tx * TNv + j];
                bb[j] = v.x; bb[j + 1] = v.y; bb[j + 2] = v.z; bb[j + 3] = v.w;
            }
            #pragma unroll
            for (int i = 0; i < TMv; i++)
                #pragma unroll
                for (int j = 0; j < TNv; j++)
                    acc[i][j] = fmaf(a[i], bb[j], acc[i][j]);
        }
        __syncthreads();
    }

    float scale = alpha;
    float* dst = C;
    if (gridDim.z > 1) { dst = Cpart + (size_t)blockIdx.z * Md * Nd; scale = 1.f; }
    #pragma unroll
    for (int i = 0; i < TMv; i++) {
        size_t row = (size_t)(m0 + ty * TMv + i) * Nd + n0 + tx * TNv;
        #pragma unroll
        for (int j = 0; j < TNv; j += 4) {
            float4 v;
            v.x = scale * acc[i][j];     v.y = scale * acc[i][j + 1];
            v.z = scale * acc[i][j + 2]; v.w = scale * acc[i][j + 3];
            *(float4*)&dst[row + j] = v;
        }
    }
}

// ---------------- software grid barrier (all NBLK blocks co-resident) ----------------
__device__ __forceinline__ void grid_barrier()
{
    __syncthreads();
    if (threadIdx.x == 0) {
        volatile unsigned* vg = &g_barg;
        unsigned gen = *vg;
        __threadfence();
        if (atomicAdd(&g_barc, 1u) == NBLK - 1) {
            g_barc = 0;
            __threadfence();
            atomicAdd(&g_barg, 1u);       // release
        } else {
            while (*vg == gen) { __nanosleep(64); }
        }
        __threadfence();
    }
    __syncthreads();
}

// ---------------- persistent forward scan ----------------
// 128 blocks x 128 threads, 1 block/SM (~184KB smem -> full wave co-resident).
// Block owns 8 h rows; W_hh slice cached in smem for ALL steps.
// Per step: stage h_t ([H][B] global) into hS[k][b] (stride HSTR=36: 16B-aligned
// float4 stores, conflict-free lanes), warps split K 4 ways, smem reduction, tanh.
__global__ void __launch_bounds__(128) rnn_scan_k(
    const float* __restrict__ h0, const float* __restrict__ Whh,
    const float* __restrict__ Xin, float* __restrict__ hT,
    float* __restrict__ Hst, float* __restrict__ hf)
{
    extern __shared__ float sm[];
    float* Ws  = sm;                        // [8][1024]
    float* hS  = sm + 8 * 1024;             // [1024][HSTR]
    float* red = hS + 1024 * HSTR;          // [4][8][33]

    const int t = threadIdx.x;
    const int lane = t & 31, w = t >> 5;
    const int hbase = blockIdx.x * 8;

    // cache Whh slice (8 rows x 1024) in smem
    for (int i = t; i < 2048; i += 128) {
        int r = i >> 8;
        int c = (i & 255) << 2;
        *(float4*)&Ws[r * 1024 + c] = *(const float4*)&Whh[(size_t)(hbase + r) * Hh + c];
    }
    // seed h0 into transposed buffer 0 and Hst[0]
    #pragma unroll
    for (int i = 0; i < 2; i++) {
        int idx = t + i * 128;
        int hr = idx >> 5, b = idx & 31;
        float v = h0[b * Hh + hbase + hr];
        hT[(hbase + hr) * Bb + b] = v;
        Hst[b * Hh + hbase + hr] = v;
    }
    grid_barrier();

    for (int tt = 0; tt < Tt; tt++) {
        const float* hin  = hT + (size_t)(tt & 1) * Hh * Bb;
        float*       hout = hT + (size_t)((tt + 1) & 1) * Hh * Bb;
        const float* xin  = Xin + (size_t)tt * BHm;

        // stage: hin[k*32+b] -> hS[k*HSTR+b].  Coalesced LDG.128, aligned STS.128.
        for (int i = t; i < 8192; i += 128) {
            int k = i >> 3;
            int bq = (i & 7) << 2;
            *(float4*)&hS[k * HSTR + bq] = *(const float4*)&hin[k * Bb + bq];
        }
        __syncthreads();

        // warp w: k in [256w, 256w+256), all 8 h rows, lane = batch
        float acc[8];
        #pragma unroll
        for (int i = 0; i < 8; i++) acc[i] = 0.f;
        const int k0 = w << 8;
        #pragma unroll 2
        for (int k = k0; k < k0 + 256; k += 4) {
            float hv0 = hS[(k + 0) * HSTR + lane];
            float hv1 = hS[(k + 1) * HSTR + lane];
            float hv2 = hS[(k + 2) * HSTR + lane];
            float hv3 = hS[(k + 3) * HSTR + lane];
            #pragma unroll
            for (int hr = 0; hr < 8; hr++) {
                float4 wv = *(const float4*)&Ws[hr * 1024 + k];   // broadcast
                acc[hr] = fmaf(hv0, wv.x, acc[hr]);
                acc[hr] = fmaf(hv1, wv.y, acc[hr]);
                acc[hr] = fmaf(hv2, wv.z, acc[hr]);
                acc[hr] = fmaf(hv3, wv.w, acc[hr]);
            }
        }
        #pragma unroll
        for (int hr = 0; hr < 8; hr++)
            red[(w * 8 + hr) * 33 + lane] = acc[hr];
        __syncthreads();

        #pragma unroll
        for (int i = 0; i < 2; i++) {
            int idx = t + i * 128;
            int hr = idx >> 5, b = idx & 31;
            float s = red[(0 * 8 + hr) * 33 + b] + red[(1 * 8 + hr) * 33 + b]
                    + red[(2 * 8 + hr) * 33 + b] + red[(3 * 8 + hr) * 33 + b];
            float v = tanhf(s + xin[b * Hh + hbase + hr]);
            hout[(hbase + hr) * Bb + b] = v;
            Hst[(size_t)(tt + 1) * BHm + b * Hh + hbase + hr] = v;
            if (tt == Tt - 1) hf[b * Hh + hbase + hr] = v;
        }
        grid_barrier();
    }
}

// ---------------- small elementwise kernels ----------------
__global__ void err_k(const float* __restrict__ ys, const float* __restrict__ tgt,
                      float* __restrict__ e)
{
    int idx = blockIdx.x * blockDim.x + threadIdx.x;
    e[idx] = ys[idx] - tgt[idx];
}

// c = (Err @ Wout) * (1 - Hnew^2)   (the GEMM part done by gemm_k into Cb)
__global__ void c_post_k(float* __restrict__ Cb, const float* __restrict__ Hst)
{
    size_t idx = (size_t)blockIdx.x * blockDim.x + threadIdx.x;
    float hn = Hst[BHm + idx];
    Cb[idx] *= (1.f - hn * hn);
}

// A[s] = c[s] + D[s+1]*A[s+1],  D[s+1] = diag(W_hh) * (1 - Hstate[s+1]^2)
__global__ void back_scan_k(float* __restrict__ Cb, const float* __restrict__ Hst,
                            const float* __restrict__ Whh)
{
    int idx = blockIdx.x * blockDim.x + threadIdx.x;   // b*H + h
    int h = idx & 1023;
    float dw = Whh[(size_t)h * Hh + h];
    float a = Cb[(size_t)(Tt - 1) * BHm + idx];
    for (int s = Tt - 2; s >= 0; s--) {
        float hn = Hst[(size_t)(s + 1) * BHm + idx];
        float d = dw * (1.f - hn * hn);
        a = Cb[(size_t)s * BHm + idx] + d * a;
        Cb[(size_t)s * BHm + idx] = a;
    }
}

__global__ void reduce_k(const float* __restrict__ part, float* __restrict__ out,
                         int MN, int S, float alpha)
{
    int i = blockIdx.x * blockDim.x + threadIdx.x;
    if (i < MN) {
        float s = 0.f;
        for (int z = 0; z < S; z++) s += part[(size_t)z * MN + i];
        out[i] = alpha * s;
    }
}

// ---------------- orchestration ----------------
extern "C" void kernel_launch(void* const* d_in, const int* in_sizes, int n_in,
                              void* d_out, int out_size)
{
    const float* x    = (const float*)d_in[0];   // [T,B,I]
    const float* tgt  = (const float*)d_in[1];   // [T,B,O]
    const float* h0   = (const float*)d_in[2];   // [B,H]
    const float* Win  = (const float*)d_in[3];   // [H,I]
    const float* Whh  = (const float*)d_in[4];   // [H,H]
    const float* Wout = (const float*)d_in[5];   // [O,H]

    float* out   = (float*)d_out;
    float* ys    = out;                      // [T*B, O]
    float* hf    = ys + (size_t)TBm * Oo;    // [B, H]
    float* gwout = hf + BHm;                 // [O, H]
    float* gwih  = gwout + (size_t)Oo * Hh;  // [H, I]
    float* gwhh  = gwih + (size_t)Hh * Ii;   // [H, H]

    float *Hst, *hT, *Xin, *Cb, *Err, *Part;
    cudaGetSymbolAddress((void**)&Hst,  g_Hstate);
    cudaGetSymbolAddress((void**)&hT,   g_hT);
    cudaGetSymbolAddress((void**)&Xin,  g_Xin);
    cudaGetSymbolAddress((void**)&Cb,   g_Cb);
    cudaGetSymbolAddress((void**)&Err,  g_Err);
    cudaGetSymbolAddress((void**)&Part, g_Part);

    // persistent scan needs >48KB dynamic smem
    const int scan_smem = (8 * 1024 + 1024 * HSTR + 32 * 33) * (int)sizeof(float);
    cudaFuncSetAttribute(rnn_scan_k, cudaFuncAttributeMaxDynamicSharedMemorySize,
                         scan_smem);

    // Xin = x @ Win^T   (NT: M=4096, N=1024, K=256)
    gemm_k<1,128,128,8,8,8><<<dim3(Hh/128, TBm/128, 1), 256>>>(
        x, Win, Xin, nullptr, TBm, Hh, Ii, 1.f, Ii);

    // persistent forward scan (fuses h0 transpose + all 128 steps + hf)
    rnn_scan_k<<<NBLK, 128, scan_smem>>>(h0, Whh, Xin, hT, Hst, hf);

    // ys = Hnew @ Wout^T  (NT: M=4096, N=128, K=1024)
    gemm_k<1,64,64,16,4,4><<<dim3(Oo/64, TBm/64, 1), 256>>>(
        Hst + BHm, Wout, ys, nullptr, TBm, Oo, Hh, 1.f, Hh);
    err_k<<<(TBm*Oo)/256, 256>>>(ys, tgt, Err);

    // c = (Err @ Wout) * php     [rank-128 collapse of (Hnew@M - Zl)]
    gemm_k<0,128,128,8,8,8><<<dim3(Hh/128, TBm/128, 1), 256>>>(
        Err, Wout, Cb, nullptr, TBm, Hh, Oo, 1.f, Oo);
    c_post_k<<<((size_t)TBm*Hh)/256, 256>>>(Cb, Hst);

    // backward scan: A[s] = c[s] + D[s+1]*A[s+1] (in-place in Cb)
    back_scan_k<<<BHm/256, 256>>>(Cb, Hst, Whh);

    // g_wih = (1e-3/B) * A^T @ x   (TN: M=1024, N=256, K=4096, split 4)
    gemm_k<2,64,64,16,4,4><<<dim3(Ii/64, Hh/64, 4), 256>>>(
        Cb, x, nullptr, Part, Hh, Ii, TBm, 0.f, TBm/4);
    reduce_k<<<(Hh*Ii + 255)/256, 256>>>(Part, gwih, Hh*Ii, 4, 1e-3f/Bb);

    // g_whh = (1e-5/B) * A^T @ Hprev  (TN: M=N=1024, K=4096, split 4)
    gemm_k<2,128,128,8,8,8><<<dim3(Hh/128, Hh/128, 4), 256>>>(
        Cb, Hst, nullptr, Part, Hh, Hh, TBm, 0.f, TBm/4);
    reduce_k<<<(Hh*Hh + 255)/256, 256>>>(Part, gwhh, Hh*Hh, 4, 1e-5f/Bb);

    // g_wout = (1/B) * Err^T @ Hnew  (TN: M=128, N=1024, K=4096, split 8)
    gemm_k<2,64,64,16,4,4><<<dim3(Hh/64, Oo/64, 8), 256>>>(
        Err, Hst + BHm, nullptr, Part, Oo, Hh, TBm, 0.f, TBm/8);
    reduce_k<<<(Oo*Hh + 255)/256, 256>>>(Part, gwout, Oo*Hh, 8, 1.f/Bb);
}

// round 5
// speedup vs baseline: 1.7817x; 1.2850x over previous
#include <cuda_runtime.h>
#include <math.h>

#define Tt 128
#define Bb 32
#define Ii 256
#define Hh 1024
#define Oo 128
#define TBm (Tt*Bb)      /* 4096 */
#define BHm (Bb*Hh)      /* 32768 */
#define NBLK 128
#define HSTR 36          /* hS row stride: multiple of 4 -> float4-aligned */

// ---------------- scratch (device globals; no allocations allowed) ----------------
static __device__ float g_Hstate[(Tt+1)*BHm];      // [t][b][h], t=0..T
static __device__ float g_hT[2*Hh*Bb];             // ping-pong transposed state [h][b]
static __device__ float g_Xin[(size_t)TBm*Hh];     // x @ W_in^T, [t*B+b][h]
static __device__ float g_Cb[(size_t)TBm*Hh];      // c then A (in-place)
static __device__ float g_Err[TBm*Oo];
static __device__ float g_Part[4*(size_t)Hh*Hh];   // split-K partials
static __device__ unsigned g_barc = 0;
static __device__ unsigned g_barg = 0;

// ---------------- double-buffered fp32 tiled GEMM ----------------
// MODE 0 = NN: C[m,n] = sum_k A[m,k]*B[k,n]
// MODE 1 = NT: C[m,n] = sum_k A[m,k]*B[n,k]
// MODE 2 = TN: C[m,n] = sum_k A[k,m]*B[k,n]
// EPI  0 = plain; 1 = also write eout = val - aux (err fusion);
//      2 = val *= (1 - aux^2)  (tanh' fusion)
// gridDim.z > 1: raw partials to Cpart[z][M*N] (alpha applied in reduce_k).
template<int MODE, int BM, int BN, int BK, int TMv, int TNv, int EPI>
__global__ __launch_bounds__(256) void gemm_k(
    const float* __restrict__ A, const float* __restrict__ B,
    float* __restrict__ C, float* __restrict__ Cpart,
    const float* __restrict__ aux, float* __restrict__ eout,
    int Md, int Nd, int Kd, float alpha, int kslice)
{
    constexpr int NA = BM * BK / 1024;      // float4 loads per thread for A tile
    constexpr int NB = BN * BK / 1024;
    __shared__ float As[2][BK][BM];
    __shared__ float Bs[2][BK][BN];
    const int t  = threadIdx.x;
    const int tx = t & 15, ty = t >> 4;
    const int m0 = blockIdx.y * BM, n0 = blockIdx.x * BN;
    const int kbeg = blockIdx.z * kslice;
    const int kend = kbeg + kslice;

    float4 pa[NA], pb[NB];

    auto ldg_tile = [&](int kk) {
        #pragma unroll
        for (int i = 0; i < NA; i++) {
            int lin = t + i * 256;
            if (MODE == 0 || MODE == 1) {            // A[m,k]
                int kv = BK / 4, m = lin / kv, kq = (lin % kv) * 4;
                pa[i] = *(const float4*)&A[(size_t)(m0 + m) * Kd + kk + kq];
            } else {                                 // A[k,m]
                int mv = BM / 4, k = lin / mv, mq = (lin % mv) * 4;
                pa[i] = *(const float4*)&A[(size_t)(kk + k) * Md + m0 + mq];
            }
        }
        #pragma unroll
        for (int i = 0; i < NB; i++) {
            int lin = t + i * 256;
            if (MODE == 0 || MODE == 2) {            // B[k,n]
                int nv = BN / 4, k = lin / nv, nq = (lin % nv) * 4;
                pb[i] = *(const float4*)&B[(size_t)(kk + k) * Nd + n0 + nq];
            } else {                                 // B[n,k]
                int kv = BK / 4, n = lin / kv, kq = (lin % kv) * 4;
                pb[i] = *(const float4*)&B[(size_t)(n0 + n) * Kd + kk + kq];
            }
        }
    };
    auto sts_tile = [&](int buf) {
        #pragma unroll
        for (int i = 0; i < NA; i++) {
            int lin = t + i * 256;
            if (MODE == 0 || MODE == 1) {
                int kv = BK / 4, m = lin / kv, kq = (lin % kv) * 4;
                As[buf][kq + 0][m] = pa[i].x; As[buf][kq + 1][m] = pa[i].y;
                As[buf][kq + 2][m] = pa[i].z; As[buf][kq + 3][m] = pa[i].w;
            } else {
                int mv = BM / 4, k = lin / mv, mq = (lin % mv) * 4;
                *(float4*)&As[buf][k][mq] = pa[i];
            }
        }
        #pragma unroll
        for (int i = 0; i < NB; i++) {
            int lin = t + i * 256;
            if (MODE == 0 || MODE == 2) {
                int nv = BN / 4, k = lin / nv, nq = (lin % nv) * 4;
                *(float4*)&Bs[buf][k][nq] = pb[i];
            } else {
                int kv = BK / 4, n = lin / kv, kq = (lin % kv) * 4;
                Bs[buf][kq + 0][n] = pb[i].x; Bs[buf][kq + 1][n] = pb[i].y;
                Bs[buf][kq + 2][n] = pb[i].z; Bs[buf][kq + 3][n] = pb[i].w;
            }
        }
    };

    float acc[TMv][TNv];
    #pragma unroll
    for (int i = 0; i < TMv; i++)
        #pragma unroll
        for (int j = 0; j < TNv; j++) acc[i][j] = 0.f;

    ldg_tile(kbeg);
    sts_tile(0);
    __syncthreads();

    int buf = 0;
    for (int kk = kbeg; kk < kend; kk += BK) {
        const bool more = (kk + BK < kend);
        if (more) ldg_tile(kk + BK);

        #pragma unroll
        for (int k = 0; k < BK; k++) {
            float a[TMv], bb[TNv];
            #pragma unroll
            for (int i = 0; i < TMv; i += 4) {
                float4 v = *(const float4*)&As[buf][k][ty * TMv + i];
                a[i] = v.x; a[i + 1] = v.y; a[i + 2] = v.z; a[i + 3] = v.w;
            }
            #pragma unroll
            for (int j = 0; j < TNv; j += 4) {
                float4 v = *(const float4*)&Bs[buf][k][tx * TNv + j];
                bb[j] = v.x; bb[j + 1] = v.y; bb[j + 2] = v.z; bb[j + 3] = v.w;
            }
            #pragma unroll
            for (int i = 0; i < TMv; i++)
                #pragma unroll
                for (int j = 0; j < TNv; j++)
                    acc[i][j] = fmaf(a[i], bb[j], acc[i][j]);
        }

        if (more) sts_tile(buf ^ 1);
        __syncthreads();
        buf ^= 1;
    }

    float scale = alpha;
    float* dst = C;
    if (gridDim.z > 1) { dst = Cpart + (size_t)blockIdx.z * Md * Nd; scale = 1.f; }
    #pragma unroll
    for (int i = 0; i < TMv; i++) {
        size_t row = (size_t)(m0 + ty * TMv + i) * Nd + n0 + tx * TNv;
        #pragma unroll
        for (int j = 0; j < TNv; j += 4) {
            float4 v;
            v.x = scale * acc[i][j];     v.y = scale * acc[i][j + 1];
            v.z = scale * acc[i][j + 2]; v.w = scale * acc[i][j + 3];
            if (EPI == 2) {
                float4 hn = *(const float4*)&aux[row + j];
                v.x *= (1.f - hn.x * hn.x); v.y *= (1.f - hn.y * hn.y);
                v.z *= (1.f - hn.z * hn.z); v.w *= (1.f - hn.w * hn.w);
            }
            *(float4*)&dst[row + j] = v;
            if (EPI == 1) {
                float4 z = *(const float4*)&aux[row + j];
                float4 e;
                e.x = v.x - z.x; e.y = v.y - z.y; e.z = v.z - z.z; e.w = v.w - z.w;
                *(float4*)&eout[row + j] = e;
            }
        }
    }
}

// ---------------- software grid barrier (all NBLK blocks co-resident) ----------------
__device__ __forceinline__ void grid_barrier()
{
    __syncthreads();
    if (threadIdx.x == 0) {
        volatile unsigned* vg = &g_barg;
        unsigned gen = *vg;
        __threadfence();
        if (atomicAdd(&g_barc, 1u) == NBLK - 1) {
            g_barc = 0;
            __threadfence();
            atomicAdd(&g_barg, 1u);       // release
        } else {
            while (*vg == gen) { __nanosleep(64); }
        }
        __threadfence();
    }
    __syncthreads();
}

// ---------------- persistent forward scan ----------------
// 128 blocks x 256 threads, 1 block/SM (~185KB smem -> full wave co-resident).
// Block owns 8 h rows; W_hh slice cached in smem for ALL steps.
// 8 warps split K 8 ways (2 warps/SMSP -> full FFMA dual-issue rate).
__global__ void __launch_bounds__(256) rnn_scan_k(
    const float* __restrict__ h0, const float* __restrict__ Whh,
    const float* __restrict__ Xin, float* __restrict__ hT,
    float* __restrict__ Hst, float* __restrict__ hf)
{
    extern __shared__ float sm[];
    float* Ws  = sm;                        // [8][1024]
    float* hS  = sm + 8 * 1024;             // [1024][HSTR]
    float* red = hS + 1024 * HSTR;          // [8][8][33]

    const int t = threadIdx.x;
    const int lane = t & 31, w = t >> 5;
    const int hbase = blockIdx.x * 8;

    // cache Whh slice (8 rows x 1024) in smem
    for (int i = t; i < 2048; i += 256) {
        int r = i >> 8;
        int c = (i & 255) << 2;
        *(float4*)&Ws[r * 1024 + c] = *(const float4*)&Whh[(size_t)(hbase + r) * Hh + c];
    }
    // seed h0 into transposed buffer 0 and Hst[0]   (256 threads = 8h x 32b)
    {
        int hr = t >> 5, b = t & 31;
        float v = h0[b * Hh + hbase + hr];
        hT[(hbase + hr) * Bb + b] = v;
        Hst[b * Hh + hbase + hr] = v;
    }
    grid_barrier();

    for (int tt = 0; tt < Tt; tt++) {
        const float* hin  = hT + (size_t)(tt & 1) * Hh * Bb;
        float*       hout = hT + (size_t)((tt + 1) & 1) * Hh * Bb;
        const float* xin  = Xin + (size_t)tt * BHm;

        // stage: hin[k*32+b] -> hS[k*HSTR+b].  Coalesced LDG.128, aligned STS.128.
        for (int i = t; i < 8192; i += 256) {
            int k = i >> 3;
            int bq = (i & 7) << 2;
            *(float4*)&hS[k * HSTR + bq] = *(const float4*)&hin[k * Bb + bq];
        }
        __syncthreads();

        // warp w: k in [128w, 128w+128), all 8 h rows, lane = batch
        float acc[8];
        #pragma unroll
        for (int i = 0; i < 8; i++) acc[i] = 0.f;
        const int k0 = w << 7;
        #pragma unroll 4
        for (int k = k0; k < k0 + 128; k += 4) {
            float hv0 = hS[(k + 0) * HSTR + lane];
            float hv1 = hS[(k + 1) * HSTR + lane];
            float hv2 = hS[(k + 2) * HSTR + lane];
            float hv3 = hS[(k + 3) * HSTR + lane];
            #pragma unroll
            for (int hr = 0; hr < 8; hr++) {
                float4 wv = *(const float4*)&Ws[hr * 1024 + k];   // broadcast
                acc[hr] = fmaf(hv0, wv.x, acc[hr]);
                acc[hr] = fmaf(hv1, wv.y, acc[hr]);
                acc[hr] = fmaf(hv2, wv.z, acc[hr]);
                acc[hr] = fmaf(hv3, wv.w, acc[hr]);
            }
        }
        #pragma unroll
        for (int hr = 0; hr < 8; hr++)
            red[(w * 8 + hr) * 33 + lane] = acc[hr];
        __syncthreads();

        {
            int hr = t >> 5, b = t & 31;
            float s = 0.f;
            #pragma unroll
            for (int wi = 0; wi < 8; wi++)
                s += red[(wi * 8 + hr) * 33 + b];
            float v = tanhf(s + xin[b * Hh + hbase + hr]);
            hout[(hbase + hr) * Bb + b] = v;
            Hst[(size_t)(tt + 1) * BHm + b * Hh + hbase + hr] = v;
            if (tt == Tt - 1) hf[b * Hh + hbase + hr] = v;
        }
        grid_barrier();
    }
}

// ---------------- small kernels ----------------
// A[s] = c[s] + D[s+1]*A[s+1],  D[s+1] = diag(W_hh) * (1 - Hstate[s+1]^2)
__global__ void back_scan_k(float* __restrict__ Cb, const float* __restrict__ Hst,
                            const float* __restrict__ Whh)
{
    int idx = blockIdx.x * blockDim.x + threadIdx.x;   // b*H + h
    int h = idx & 1023;
    float dw = Whh[(size_t)h * Hh + h];
    float a = Cb[(size_t)(Tt - 1) * BHm + idx];
    for (int s = Tt - 2; s >= 0; s--) {
        float hn = Hst[(size_t)(s + 1) * BHm + idx];
        float d = dw * (1.f - hn * hn);
        a = Cb[(size_t)s * BHm + idx] + d * a;
        Cb[(size_t)s * BHm + idx] = a;
    }
}

__global__ void reduce_k(const float* __restrict__ part, float* __restrict__ out,
                         int MN, int S, float alpha)
{
    int i = blockIdx.x * blockDim.x + threadIdx.x;
    if (i < MN) {
        float s = 0.f;
        for (int z = 0; z < S; z++) s += part[(size_t)z * MN + i];
        out[i] = alpha * s;
    }
}

// ---------------- orchestration ----------------
extern "C" void kernel_launch(void* const* d_in, const int* in_sizes, int n_in,
                              void* d_out, int out_size)
{
    const float* x    = (const float*)d_in[0];   // [T,B,I]
    const float* tgt  = (const float*)d_in[1];   // [T,B,O]
    const float* h0   = (const float*)d_in[2];   // [B,H]
    const float* Win  = (const float*)d_in[3];   // [H,I]
    const float* Whh  = (const float*)d_in[4];   // [H,H]
    const float* Wout = (const float*)d_in[5];   // [O,H]

    float* out   = (float*)d_out;
    float* ys    = out;                      // [T*B, O]
    float* hf    = ys + (size_t)TBm * Oo;    // [B, H]
    float* gwout = hf + BHm;                 // [O, H]
    float* gwih  = gwout + (size_t)Oo * Hh;  // [H, I]
    float* gwhh  = gwih + (size_t)Hh * Ii;   // [H, H]

    float *Hst, *hT, *Xin, *Cb, *Err, *Part;
    cudaGetSymbolAddress((void**)&Hst,  g_Hstate);
    cudaGetSymbolAddress((void**)&hT,   g_hT);
    cudaGetSymbolAddress((void**)&Xin,  g_Xin);
    cudaGetSymbolAddress((void**)&Cb,   g_Cb);
    cudaGetSymbolAddress((void**)&Err,  g_Err);
    cudaGetSymbolAddress((void**)&Part, g_Part);

    // persistent scan needs >48KB dynamic smem
    const int scan_smem = (8 * 1024 + 1024 * HSTR + 64 * 33) * (int)sizeof(float);
    cudaFuncSetAttribute(rnn_scan_k, cudaFuncAttributeMaxDynamicSharedMemorySize,
                         scan_smem);

    // Xin = x @ Win^T   (NT: M=4096, N=1024, K=256)
    gemm_k<1,128,128,16,8,8,0><<<dim3(Hh/128, TBm/128, 1), 256>>>(
        x, Win, Xin, nullptr, nullptr, nullptr, TBm, Hh, Ii, 1.f, Ii);

    // persistent forward scan (fuses h0 transpose + all 128 steps + hf)
    rnn_scan_k<<<NBLK, 256, scan_smem>>>(h0, Whh, Xin, hT, Hst, hf);

    // ys = Hnew @ Wout^T, fused Err = ys - tgt  (NT: M=4096, N=128, K=1024)
    gemm_k<1,64,64,16,4,4,1><<<dim3(Oo/64, TBm/64, 1), 256>>>(
        Hst + BHm, Wout, ys, nullptr, tgt, Err, TBm, Oo, Hh, 1.f, Hh);

    // c = (Err @ Wout) * (1 - Hnew^2)   [rank-128 collapse, fused tanh']
    gemm_k<0,128,128,16,8,8,2><<<dim3(Hh/128, TBm/128, 1), 256>>>(
        Err, Wout, Cb, nullptr, Hst + BHm, nullptr, TBm, Hh, Oo, 1.f, Oo);

    // backward scan: A[s] = c[s] + D[s+1]*A[s+1] (in-place in Cb)
    back_scan_k<<<BHm/256, 256>>>(Cb, Hst, Whh);

    // g_wih = (1e-3/B) * A^T @ x   (TN: M=1024, N=256, K=4096, split 4)
    gemm_k<2,64,64,16,4,4,0><<<dim3(Ii/64, Hh/64, 4), 256>>>(
        Cb, x, nullptr, Part, nullptr, nullptr, Hh, Ii, TBm, 0.f, TBm/4);
    reduce_k<<<(Hh*Ii + 255)/256, 256>>>(Part, gwih, Hh*Ii, 4, 1e-3f/Bb);

    // g_whh = (1e-5/B) * A^T @ Hprev  (TN: M=N=1024, K=4096, split 4)
    gemm_k<2,128,128,16,8,8,0><<<dim3(Hh/128, Hh/128, 4), 256>>>(
        Cb, Hst, nullptr, Part, nullptr, nullptr, Hh, Hh, TBm, 0.f, TBm/4);
    reduce_k<<<(Hh*Hh + 255)/256, 256>>>(Part, gwhh, Hh*Hh, 4, 1e-5f/Bb);

    // g_wout = (1/B) * Err^T @ Hnew  (TN: M=128, N=1024, K=4096, split 8)
    gemm_k<2,64,64,16,4,4,0><<<dim3(Hh/64, Oo/64, 8), 256>>>(
        Err, Hst + BHm, nullptr, Part, nullptr, nullptr, Oo, Hh, TBm, 0.f, TBm/8);
    reduce_k<<<(Oo*Hh + 255)/256, 256>>>(Part, gwout, Oo*Hh, 8, 1.f/Bb);
}

// round 6
// speedup vs baseline: 1.9659x; 1.1034x over previous
#include <cuda_runtime.h>
#include <math.h>

#define Tt 128
#define Bb 32
#define Ii 256
#define Hh 1024
#define Oo 128
#define TBm (Tt*Bb)      /* 4096 */
#define BHm (Bb*Hh)      /* 32768 */
#define NBLK 128
#define HSTR 36          /* hS row stride: multiple of 4 -> float4-aligned */

// ---------------- scratch (device globals; no allocations allowed) ----------------
static __device__ float g_Hstate[(Tt+1)*BHm];      // [t][b][h], t=0..T
static __device__ float g_hT[2*Hh*Bb];             // ping-pong transposed state [h][b]
static __device__ float g_Xin[(size_t)TBm*Hh];     // x @ W_in^T, [t*B+b][h]
static __device__ float g_Cb[(size_t)TBm*Hh];      // c then A (in-place)
static __device__ float g_Err[TBm*Oo];
static __device__ float g_Part[4*(size_t)Hh*Hh];   // split-K partials
static __device__ unsigned g_barc = 0;
static __device__ unsigned g_barg = 0;

// ---------------- double-buffered fp32 tiled GEMM ----------------
// MODE 0 = NN: C[m,n] = sum_k A[m,k]*B[k,n]
// MODE 1 = NT: C[m,n] = sum_k A[m,k]*B[n,k]
// MODE 2 = TN: C[m,n] = sum_k A[k,m]*B[k,n]
// EPI  0 = plain; 2 = val *= (1 - aux^2)  (tanh' fusion)
// gridDim.z > 1: raw partials to Cpart[z][M*N] (alpha/EPI applied in reduce_k).
template<int MODE, int BM, int BN, int BK, int TMv, int TNv, int EPI>
__global__ __launch_bounds__(256) void gemm_k(
    const float* __restrict__ A, const float* __restrict__ B,
    float* __restrict__ C, float* __restrict__ Cpart,
    const float* __restrict__ aux,
    int Md, int Nd, int Kd, float alpha, int kslice)
{
    constexpr int NA = BM * BK / 1024;      // float4 loads per thread for A tile
    constexpr int NB = BN * BK / 1024;
    __shared__ float As[2][BK][BM];
    __shared__ float Bs[2][BK][BN];
    const int t  = threadIdx.x;
    const int tx = t & 15, ty = t >> 4;
    const int m0 = blockIdx.y * BM, n0 = blockIdx.x * BN;
    const int kbeg = blockIdx.z * kslice;
    const int kend = kbeg + kslice;

    float4 pa[NA], pb[NB];

    auto ldg_tile = [&](int kk) {
        #pragma unroll
        for (int i = 0; i < NA; i++) {
            int lin = t + i * 256;
            if (MODE == 0 || MODE == 1) {            // A[m,k]
                int kv = BK / 4, m = lin / kv, kq = (lin % kv) * 4;
                pa[i] = *(const float4*)&A[(size_t)(m0 + m) * Kd + kk + kq];
            } else {                                 // A[k,m]
                int mv = BM / 4, k = lin / mv, mq = (lin % mv) * 4;
                pa[i] = *(const float4*)&A[(size_t)(kk + k) * Md + m0 + mq];
            }
        }
        #pragma unroll
        for (int i = 0; i < NB; i++) {
            int lin = t + i * 256;
            if (MODE == 0 || MODE == 2) {            // B[k,n]
                int nv = BN / 4, k = lin / nv, nq = (lin % nv) * 4;
                pb[i] = *(const float4*)&B[(size_t)(kk + k) * Nd + n0 + nq];
            } else {                                 // B[n,k]
                int kv = BK / 4, n = lin / kv, kq = (lin % kv) * 4;
                pb[i] = *(const float4*)&B[(size_t)(n0 + n) * Kd + kk + kq];
            }
        }
    };
    auto sts_tile = [&](int buf) {
        #pragma unroll
        for (int i = 0; i < NA; i++) {
            int lin = t + i * 256;
            if (MODE == 0 || MODE == 1) {
                int kv = BK / 4, m = lin / kv, kq = (lin % kv) * 4;
                As[buf][kq + 0][m] = pa[i].x; As[buf][kq + 1][m] = pa[i].y;
                As[buf][kq + 2][m] = pa[i].z; As[buf][kq + 3][m] = pa[i].w;
            } else {
                int mv = BM / 4, k = lin / mv, mq = (lin % mv) * 4;
                *(float4*)&As[buf][k][mq] = pa[i];
            }
        }
        #pragma unroll
        for (int i = 0; i < NB; i++) {
            int lin = t + i * 256;
            if (MODE == 0 || MODE == 2) {
                int nv = BN / 4, k = lin / nv, nq = (lin % nv) * 4;
                *(float4*)&Bs[buf][k][nq] = pb[i];
            } else {
                int kv = BK / 4, n = lin / kv, kq = (lin % kv) * 4;
                Bs[buf][kq + 0][n] = pb[i].x; Bs[buf][kq + 1][n] = pb[i].y;
                Bs[buf][kq + 2][n] = pb[i].z; Bs[buf][kq + 3][n] = pb[i].w;
            }
        }
    };

    float acc[TMv][TNv];
    #pragma unroll
    for (int i = 0; i < TMv; i++)
        #pragma unroll
        for (int j = 0; j < TNv; j++) acc[i][j] = 0.f;

    ldg_tile(kbeg);
    sts_tile(0);
    __syncthreads();

    int buf = 0;
    for (int kk = kbeg; kk < kend; kk += BK) {
        const bool more = (kk + BK < kend);
        if (more) ldg_tile(kk + BK);

        #pragma unroll
        for (int k = 0; k < BK; k++) {
            float a[TMv], bb[TNv];
            #pragma unroll
            for (int i = 0; i < TMv; i += 4) {
                float4 v = *(const float4*)&As[buf][k][ty * TMv + i];
                a[i] = v.x; a[i + 1] = v.y; a[i + 2] = v.z; a[i + 3] = v.w;
            }
            #pragma unroll
            for (int j = 0; j < TNv; j += 4) {
                float4 v = *(const float4*)&Bs[buf][k][tx * TNv + j];
                bb[j] = v.x; bb[j + 1] = v.y; bb[j + 2] = v.z; bb[j + 3] = v.w;
            }
            #pragma unroll
            for (int i = 0; i < TMv; i++)
                #pragma unroll
                for (int j = 0; j < TNv; j++)
                    acc[i][j] = fmaf(a[i], bb[j], acc[i][j]);
        }

        if (more) sts_tile(buf ^ 1);
        __syncthreads();
        buf ^= 1;
    }

    float scale = alpha;
    float* dst = C;
    if (gridDim.z > 1) { dst = Cpart + (size_t)blockIdx.z * Md * Nd; scale = 1.f; }
    #pragma unroll
    for (int i = 0; i < TMv; i++) {
        size_t row = (size_t)(m0 + ty * TMv + i) * Nd + n0 + tx * TNv;
        #pragma unroll
        for (int j = 0; j < TNv; j += 4) {
            float4 v;
            v.x = scale * acc[i][j];     v.y = scale * acc[i][j + 1];
            v.z = scale * acc[i][j + 2]; v.w = scale * acc[i][j + 3];
            if (EPI == 2) {
                float4 hn = *(const float4*)&aux[row + j];
                v.x *= (1.f - hn.x * hn.x); v.y *= (1.f - hn.y * hn.y);
                v.z *= (1.f - hn.z * hn.z); v.w *= (1.f - hn.w * hn.w);
            }
            *(float4*)&dst[row + j] = v;
        }
    }
}

// ---------------- grid barrier: acq_rel arrive + release/acquire generation ----------------
// expect = absolute generation (caller reads g_barg once at kernel start, +1 per barrier)
__device__ __forceinline__ void grid_barrier(unsigned& expect)
{
    __syncthreads();
    if (threadIdx.x == 0) {
        expect += 1;
        unsigned old;
        asm volatile("atom.add.acq_rel.gpu.global.u32 %0, [%1], 1;"
                     : "=r"(old) : "l"(&g_barc) : "memory");
        if (old == NBLK - 1) {
            asm volatile("st.relaxed.gpu.global.u32 [%0], %1;"
                         :: "l"(&g_barc), "r"(0u) : "memory");
            asm volatile("st.release.gpu.global.u32 [%0], %1;"
                         :: "l"(&g_barg), "r"(expect) : "memory");
        } else {
            unsigned cur;
            do {
                asm volatile("ld.acquire.gpu.global.u32 %0, [%1];"
                             : "=r"(cur) : "l"(&g_barg) : "memory");
            } while ((int)(cur - expect) < 0);
        }
    }
    __syncthreads();
}

// ---------------- persistent forward scan ----------------
// 128 blocks x 256 threads, 1 block/SM (~185KB smem -> full wave co-resident).
// Block owns 8 h rows; W_hh slice cached in smem for ALL steps.
// Each warp stages + consumes its own 128-k slice of h (no block sync needed there).
__global__ void __launch_bounds__(256) rnn_scan_k(
    const float* __restrict__ h0, const float* __restrict__ Whh,
    const float* __restrict__ Xin, float* __restrict__ hT,
    float* __restrict__ Hst, float* __restrict__ hf)
{
    extern __shared__ float sm[];
    float* Ws  = sm;                        // [8][1024]
    float* hS  = sm + 8 * 1024;             // [1024][HSTR]
    float* red = hS + 1024 * HSTR;          // [8][8][33]

    const int t = threadIdx.x;
    const int lane = t & 31, w = t >> 5;
    const int hbase = blockIdx.x * 8;

    unsigned expect;
    if (t == 0)
        asm volatile("ld.global.u32 %0, [%1];" : "=r"(expect) : "l"(&g_barg));

    // cache Whh slice (8 rows x 1024) in smem
    for (int i = t; i < 2048; i += 256) {
        int r = i >> 8;
        int c = (i & 255) << 2;
        *(float4*)&Ws[r * 1024 + c] = *(const float4*)&Whh[(size_t)(hbase + r) * Hh + c];
    }
    // seed h0 into transposed buffer 0 and Hst[0]   (256 threads = 8h x 32b)
    {
        int hr = t >> 5, b = t & 31;
        float v = h0[b * Hh + hbase + hr];
        hT[(hbase + hr) * Bb + b] = v;
        Hst[b * Hh + hbase + hr] = v;
    }
    grid_barrier(expect);

    const int k0 = w << 7;                  // warp's k range [k0, k0+128)
    for (int tt = 0; tt < Tt; tt++) {
        const float* hin  = hT + (size_t)(tt & 1) * Hh * Bb;
        float*       hout = hT + (size_t)((tt + 1) & 1) * Hh * Bb;
        const float* xin  = Xin + (size_t)tt * BHm;

        // warp-private stage of its own k slice: hin[k*32+b] -> hS[k*HSTR+b]
        #pragma unroll 4
        for (int i = lane; i < 1024; i += 32) {
            int k = k0 + (i >> 3);
            int bq = (i & 7) << 2;
            *(float4*)&hS[k * HSTR + bq] = *(const float4*)&hin[k * Bb + bq];
        }

        // warp w: k in [k0, k0+128), all 8 h rows, lane = batch
        float acc[8];
        #pragma unroll
        for (int i = 0; i < 8; i++) acc[i] = 0.f;
        #pragma unroll 4
        for (int k = k0; k < k0 + 128; k += 4) {
            float hv0 = hS[(k + 0) * HSTR + lane];
            float hv1 = hS[(k + 1) * HSTR + lane];
            float hv2 = hS[(k + 2) * HSTR + lane];
            float hv3 = hS[(k + 3) * HSTR + lane];
            #pragma unroll
            for (int hr = 0; hr < 8; hr++) {
                float4 wv = *(const float4*)&Ws[hr * 1024 + k];   // broadcast
                acc[hr] = fmaf(hv0, wv.x, acc[hr]);
                acc[hr] = fmaf(hv1, wv.y, acc[hr]);
                acc[hr] = fmaf(hv2, wv.z, acc[hr]);
                acc[hr] = fmaf(hv3, wv.w, acc[hr]);
            }
        }
        #pragma unroll
        for (int hr = 0; hr < 8; hr++)
            red[(w * 8 + hr) * 33 + lane] = acc[hr];
        __syncthreads();

        {
            int hr = t >> 5, b = t & 31;
            float s = 0.f;
            #pragma unroll
            for (int wi = 0; wi < 8; wi++)
                s += red[(wi * 8 + hr) * 33 + b];
            float v = tanhf(s + xin[b * Hh + hbase + hr]);
            hout[(hbase + hr) * Bb + b] = v;
            Hst[(size_t)(tt + 1) * BHm + b * Hh + hbase + hr] = v;
            if (tt == Tt - 1) hf[b * Hh + hbase + hr] = v;
        }
        grid_barrier(expect);
    }
}

// ---------------- small kernels ----------------
// A[s] = c[s] + D[s+1]*A[s+1],  D[s+1] = diag(W_hh) * (1 - Hstate[s+1]^2)
__global__ void back_scan_k(float* __restrict__ Cb, const float* __restrict__ Hst,
                            const float* __restrict__ Whh)
{
    int idx = blockIdx.x * blockDim.x + threadIdx.x;   // b*H + h
    int h = idx & 1023;
    float dw = Whh[(size_t)h * Hh + h];
    float a = Cb[(size_t)(Tt - 1) * BHm + idx];
    for (int s = Tt - 2; s >= 0; s--) {
        float hn = Hst[(size_t)(s + 1) * BHm + idx];
        float d = dw * (1.f - hn * hn);
        a = Cb[(size_t)s * BHm + idx] + d * a;
        Cb[(size_t)s * BHm + idx] = a;
    }
}

// EPI 0: out = alpha * sum(part).   EPI 1: out = sum(part); eout = out - aux.
template<int EPI>
__global__ void reduce_k(const float* __restrict__ part, float* __restrict__ out,
                         const float* __restrict__ aux, float* __restrict__ eout,
                         int MN, int S, float alpha)
{
    int i = blockIdx.x * blockDim.x + threadIdx.x;
    if (i < MN) {
        float s = 0.f;
        for (int z = 0; z < S; z++) s += part[(size_t)z * MN + i];
        s *= alpha;
        out[i] = s;
        if (EPI == 1) eout[i] = s - aux[i];
    }
}

// ---------------- orchestration ----------------
extern "C" void kernel_launch(void* const* d_in, const int* in_sizes, int n_in,
                              void* d_out, int out_size)
{
    const float* x    = (const float*)d_in[0];   // [T,B,I]
    const float* tgt  = (const float*)d_in[1];   // [T,B,O]
    const float* h0   = (const float*)d_in[2];   // [B,H]
    const float* Win  = (const float*)d_in[3];   // [H,I]
    const float* Whh  = (const float*)d_in[4];   // [H,H]
    const float* Wout = (const float*)d_in[5];   // [O,H]

    float* out   = (float*)d_out;
    float* ys    = out;                      // [T*B, O]
    float* hf    = ys + (size_t)TBm * Oo;    // [B, H]
    float* gwout = hf + BHm;                 // [O, H]
    float* gwih  = gwout + (size_t)Oo * Hh;  // [H, I]
    float* gwhh  = gwih + (size_t)Hh * Ii;   // [H, H]

    float *Hst, *hT, *Xin, *Cb, *Err, *Part;
    cudaGetSymbolAddress((void**)&Hst,  g_Hstate);
    cudaGetSymbolAddress((void**)&hT,   g_hT);
    cudaGetSymbolAddress((void**)&Xin,  g_Xin);
    cudaGetSymbolAddress((void**)&Cb,   g_Cb);
    cudaGetSymbolAddress((void**)&Err,  g_Err);
    cudaGetSymbolAddress((void**)&Part, g_Part);

    // persistent scan needs >48KB dynamic smem
    const int scan_smem = (8 * 1024 + 1024 * HSTR + 64 * 33) * (int)sizeof(float);
    cudaFuncSetAttribute(rnn_scan_k, cudaFuncAttributeMaxDynamicSharedMemorySize,
                         scan_smem);

    // Xin = x @ Win^T   (NT: M=4096, N=1024, K=256)
    gemm_k<1,128,128,16,8,8,0><<<dim3(Hh/128, TBm/128, 1), 256>>>(
        x, Win, Xin, nullptr, nullptr, TBm, Hh, Ii, 1.f, Ii);

    // persistent forward scan (fuses h0 transpose + all 128 steps + hf)
    rnn_scan_k<<<NBLK, 256, scan_smem>>>(h0, Whh, Xin, hT, Hst, hf);

    // ys = Hnew @ Wout^T  (NT: M=4096, N=128, K=1024, 128x64 tiles, split-K 2)
    gemm_k<1,128,64,16,8,4,0><<<dim3(Oo/64, TBm/128, 2), 256>>>(
        Hst + BHm, Wout, nullptr, Part, nullptr, TBm, Oo, Hh, 0.f, Hh/2);
    // reduce + fused Err = ys - tgt
    reduce_k<1><<<(TBm*Oo + 255)/256, 256>>>(Part, ys, tgt, Err, TBm*Oo, 2, 1.f);

    // c = (Err @ Wout) * (1 - Hnew^2)   [rank-128 collapse, fused tanh']
    gemm_k<0,128,128,16,8,8,2><<<dim3(Hh/128, TBm/128, 1), 256>>>(
        Err, Wout, Cb, nullptr, Hst + BHm, TBm, Hh, Oo, 1.f, Oo);

    // backward scan: A[s] = c[s] + D[s+1]*A[s+1] (in-place in Cb)
    back_scan_k<<<BHm/256, 256>>>(Cb, Hst, Whh);

    // g_wih = (1e-3/B) * A^T @ x   (TN: M=1024, N=256, K=4096, 128x128, split 8)
    gemm_k<2,128,128,16,8,8,0><<<dim3(Ii/128, Hh/128, 8), 256>>>(
        Cb, x, nullptr, Part, nullptr, Hh, Ii, TBm, 0.f, TBm/8);
    reduce_k<0><<<(Hh*Ii + 255)/256, 256>>>(Part, gwih, nullptr, nullptr,
                                            Hh*Ii, 8, 1e-3f/Bb);

    // g_whh = (1e-5/B) * A^T @ Hprev  (TN: M=N=1024, K=4096, 128x128, split 4)
    gemm_k<2,128,128,16,8,8,0><<<dim3(Hh/128, Hh/128, 4), 256>>>(
        Cb, Hst, nullptr, Part, nullptr, Hh, Hh, TBm, 0.f, TBm/4);
    reduce_k<0><<<(Hh*Hh + 255)/256, 256>>>(Part, gwhh, nullptr, nullptr,
                                            Hh*Hh, 4, 1e-5f/Bb);

    // g_wout = (1/B) * Err^T @ Hnew  (TN: M=128, N=1024, K=4096, 128x128, split 16)
    gemm_k<2,128,128,16,8,8,0><<<dim3(Hh/128, Oo/128, 16), 256>>>(
        Err, Hst + BHm, nullptr, Part, nullptr, Oo, Hh, TBm, 0.f, TBm/16);
    reduce_k<0><<<(Oo*Hh + 255)/256, 256>>>(Part, gwout, nullptr, nullptr,
                                            Oo*Hh, 16, 1.f/Bb);
}